// round 6
// baseline (speedup 1.0000x reference)
#include <cuda_runtime.h>
#include <math.h>

// ---------------- problem constants ----------------
#define BB    4
#define NSEQ  4096
#define MLAT  512
#define DIN   768
#define DLAT  1024
#define INNER 1024
#define HH    16
#define DH    64
#define NK    4608          // NSEQ + MLAT (concat along sequence)
#define LN_EPS  1e-5f
#define RMS_EPS 1e-8f
#define SCALE   0.125f      // 64^-0.5

// ---------------- scratch (static device memory; no allocations) ----------------
__device__ float g_xn [(size_t)BB*NSEQ*DIN];        // layernorm(x)
__device__ float g_ln [(size_t)BB*MLAT*DLAT];       // layernorm(latents)
__device__ float g_qf [(size_t)BB*MLAT*INNER];      // ln @ Wq^T   (flat)
__device__ float g_kvx[(size_t)BB*NSEQ*2*INNER];    // xn @ Wkv^T
__device__ float g_kvl[(size_t)BB*MLAT*2*INNER];    // ln @ Wlkv^T
__device__ float g_Q  [(size_t)BB*HH*MLAT*DH];      // rmsnorm'd * SCALE, [b][h][i][d]
__device__ float g_K  [(size_t)BB*HH*NK*DH];        // rmsnorm'd,        [b][h][j][d]
__device__ float g_V  [(size_t)BB*HH*NK*DH];        // [b][h][j][d]
__device__ float g_O  [(size_t)BB*MLAT*INNER];      // attention out, [b][i][h*64+d]
__device__ int   g_mask_u8;                         // 1 = mask is byte-packed

// ---------------- mask dtype detection ----------------
__global__ void init_flag_kernel() { g_mask_u8 = 0; }

// If the bool mask were widened to int32, every word is 0 or 1.
// If it is byte-packed, the first 4096 int32 views are byte quadruples and
// (with a random 0/1 mask) will contain values > 1 with overwhelming probability.
__global__ void detect_mask_kernel(const int* __restrict__ m) {
    int i = blockIdx.x * blockDim.x + threadIdx.x;   // scan first 4096 words (16KB, in bounds either way)
    if (i < 4096) {
        unsigned v = (unsigned)m[i];
        if (v > 1u) atomicExch(&g_mask_u8, 1);
    }
}

// ---------------- layernorm (one row per block, 256 threads) ----------------
__global__ __launch_bounds__(256)
void ln_kernel(const float* __restrict__ x, const float* __restrict__ g,
               const float* __restrict__ b, float* __restrict__ out, int C) {
    int row = blockIdx.x;
    const float* xr = x + (size_t)row * C;
    float* orow = out + (size_t)row * C;
    int C4 = C >> 2;
    float s = 0.f, s2 = 0.f;
    for (int i = threadIdx.x; i < C4; i += 256) {
        float4 v = ((const float4*)xr)[i];
        s  += v.x + v.y + v.z + v.w;
        s2 += v.x*v.x + v.y*v.y + v.z*v.z + v.w*v.w;
    }
    __shared__ float red0[8], red1[8];
    #pragma unroll
    for (int o = 16; o; o >>= 1) {
        s  += __shfl_xor_sync(0xffffffffu, s,  o);
        s2 += __shfl_xor_sync(0xffffffffu, s2, o);
    }
    int w = threadIdx.x >> 5, l = threadIdx.x & 31;
    if (l == 0) { red0[w] = s; red1[w] = s2; }
    __syncthreads();
    if (threadIdx.x == 0) {
        float a = 0.f, c = 0.f;
        #pragma unroll
        for (int k = 0; k < 8; k++) { a += red0[k]; c += red1[k]; }
        red0[0] = a; red1[0] = c;
    }
    __syncthreads();
    float mu  = red0[0] / (float)C;
    float var = red1[0] / (float)C - mu * mu;
    float rstd = rsqrtf(var + LN_EPS);
    for (int i = threadIdx.x; i < C4; i += 256) {
        float4 v  = ((const float4*)xr)[i];
        float4 gg = ((const float4*)g)[i];
        float4 bb = ((const float4*)b)[i];
        float4 o;
        o.x = (v.x - mu) * rstd * gg.x + bb.x;
        o.y = (v.y - mu) * rstd * gg.y + bb.y;
        o.z = (v.z - mu) * rstd * gg.z + bb.z;
        o.w = (v.w - mu) * rstd * gg.w + bb.w;
        ((float4*)orow)[i] = o;
    }
}

// ---------------- generic C[M,N] = A[M,K] * B[N,K]^T (+bias) ----------------
// 64x64 tile, BK=16, 256 threads, 4x4 per thread.
// Global loads for tile t+1 are prefetched into registers during tile t's FMAs.
__global__ __launch_bounds__(256)
void gemm_abt_kernel(const float* __restrict__ A, const float* __restrict__ Bm,
                     float* __restrict__ C, int M, int N, int K,
                     const float* __restrict__ bias) {
    __shared__ __align__(16) float As[16][68];
    __shared__ __align__(16) float Bs[16][68];
    int bm = blockIdx.y << 6, bn = blockIdx.x << 6;
    int tid = threadIdx.x;
    int ty = tid >> 4, tx = tid & 15;
    int arow = tid >> 2;          // 0..63
    int ak4  = tid & 3;           // 0..3
    const float* Aptr = A  + (size_t)(bm + arow) * K + ak4 * 4;
    const float* Bptr = Bm + (size_t)(bn + arow) * K + ak4 * 4;
    float acc[4][4] = {};
    int k0 = ak4 << 2;

    // preload k-tile 0
    float4 av = *(const float4*)(Aptr);
    float4 bv = *(const float4*)(Bptr);

    for (int kt = 0; kt < K; kt += 16) {
        As[k0+0][arow] = av.x; As[k0+1][arow] = av.y;
        As[k0+2][arow] = av.z; As[k0+3][arow] = av.w;
        Bs[k0+0][arow] = bv.x; Bs[k0+1][arow] = bv.y;
        Bs[k0+2][arow] = bv.z; Bs[k0+3][arow] = bv.w;
        __syncthreads();

        // prefetch next k-tile while computing this one
        // (last iteration: clamp to current tile — always in-bounds, value unused)
        int ktn = (kt + 16 < K) ? (kt + 16) : kt;
        av = *(const float4*)(Aptr + ktn);
        bv = *(const float4*)(Bptr + ktn);

        #pragma unroll
        for (int k = 0; k < 16; k++) {
            float4 af = *(const float4*)&As[k][ty << 2];
            float4 bf = *(const float4*)&Bs[k][tx << 2];
            acc[0][0] += af.x*bf.x; acc[0][1] += af.x*bf.y; acc[0][2] += af.x*bf.z; acc[0][3] += af.x*bf.w;
            acc[1][0] += af.y*bf.x; acc[1][1] += af.y*bf.y; acc[1][2] += af.y*bf.z; acc[1][3] += af.y*bf.w;
            acc[2][0] += af.z*bf.x; acc[2][1] += af.z*bf.y; acc[2][2] += af.z*bf.z; acc[2][3] += af.z*bf.w;
            acc[3][0] += af.w*bf.x; acc[3][1] += af.w*bf.y; acc[3][2] += af.w*bf.z; acc[3][3] += af.w*bf.w;
        }
        __syncthreads();
    }
    float4 bias4 = make_float4(0.f, 0.f, 0.f, 0.f);
    if (bias) bias4 = *(const float4*)&bias[bn + (tx << 2)];
    #pragma unroll
    for (int i = 0; i < 4; i++) {
        float4 o;
        o.x = acc[i][0] + bias4.x; o.y = acc[i][1] + bias4.y;
        o.z = acc[i][2] + bias4.z; o.w = acc[i][3] + bias4.w;
        *(float4*)&C[(size_t)(bm + (ty << 2) + i) * N + bn + (tx << 2)] = o;
    }
}

// ---------------- Q scatter: rmsnorm per head * SCALE, [b][h][i][d] ----------------
__global__ __launch_bounds__(256)
void q_scatter_kernel(const float* __restrict__ qn_g) {
    int row = blockIdx.x;              // 0..2047  (b*512 + i)
    int b = row >> 9, i = row & 511;
    int tid = threadIdx.x;
    int h = tid >> 4, lane = tid & 15, d0 = lane << 2;
    float4 v = *(const float4*)&g_qf[(size_t)row * INNER + h * DH + d0];
    float ss = v.x*v.x + v.y*v.y + v.z*v.z + v.w*v.w;
    #pragma unroll
    for (int o = 8; o; o >>= 1) ss += __shfl_xor_sync(0xffffffffu, ss, o);
    float norm = sqrtf(ss) * 0.125f;
    float inv = SCALE / fmaxf(norm, RMS_EPS);
    float4 g4 = *(const float4*)&qn_g[d0];
    float4 o;
    o.x = v.x * inv * g4.x; o.y = v.y * inv * g4.y;
    o.z = v.z * inv * g4.z; o.w = v.w * inv * g4.w;
    *(float4*)&g_Q[((size_t)(b * HH + h) * MLAT + i) * DH + d0] = o;
}

// ---------------- K/V scatter: K gets rmsnorm, V is a copy ----------------
__global__ __launch_bounds__(512)
void kv_scatter_kernel(const float* __restrict__ kn_g) {
    int row = blockIdx.x;              // 0..18431  (b*4608 + j)
    int b = row / NK, j = row - b * NK;
    const float* src = (j < NSEQ)
        ? &g_kvx[((size_t)b * NSEQ + j) * (2 * INNER)]
        : &g_kvl[((size_t)b * MLAT + (j - NSEQ)) * (2 * INNER)];
    int tid = threadIdx.x;
    if (tid < 256) {                   // K half with rmsnorm
        int h = tid >> 4, lane = tid & 15, d0 = lane << 2;
        float4 v = *(const float4*)&src[h * DH + d0];
        float ss = v.x*v.x + v.y*v.y + v.z*v.z + v.w*v.w;
        #pragma unroll
        for (int o = 8; o; o >>= 1) ss += __shfl_xor_sync(0xffffffffu, ss, o);
        float norm = sqrtf(ss) * 0.125f;
        float inv = 1.0f / fmaxf(norm, RMS_EPS);
        float4 g4 = *(const float4*)&kn_g[d0];
        float4 o;
        o.x = v.x * inv * g4.x; o.y = v.y * inv * g4.y;
        o.z = v.z * inv * g4.z; o.w = v.w * inv * g4.w;
        *(float4*)&g_K[((size_t)(b * HH + h) * NK + j) * DH + d0] = o;
    } else {                           // V half, plain copy
        int t = tid - 256;
        int h = t >> 4, lane = t & 15, d0 = lane << 2;
        float4 v = *(const float4*)&src[INNER + h * DH + d0];
        *(float4*)&g_V[((size_t)(b * HH + h) * NK + j) * DH + d0] = v;
    }
}

// ---------------- flash attention: 64 queries x 64 keys per tile ----------------
// smem floats: Qst 64*68 | Kst 64*68 | Vs 64*64 | Ss 64*67 | rowm/rowl/alpha 3*64 | maskadd 64
#define ATTN_SMEM_FLOATS (64*68*2 + 64*64 + 64*67 + 4*64)
__global__ __launch_bounds__(256)
void attn_kernel(const unsigned char* __restrict__ m8, const int* __restrict__ m32) {
    extern __shared__ __align__(16) float sm[];
    float* Qst = sm;                       // [d][q], pad 68
    float* Kst = Qst + 64 * 68;            // [d][j], pad 68
    float* Vs  = Kst + 64 * 68;            // [j][d], stride 64
    float* Ss  = Vs  + 64 * 64;            // [q][j], pad 67
    float* rowm = Ss + 64 * 67;
    float* rowl = rowm + 64;
    float* alph = rowl + 64;
    float* maskadd = alph + 64;

    int b = blockIdx.z, h = blockIdx.y;
    int q0 = blockIdx.x << 6;
    int bh = b * HH + h;
    const size_t Kbase = (size_t)bh * NK * DH;
    const size_t Qbase = ((size_t)bh * MLAT + q0) * DH;
    int tid = threadIdx.x;
    int ty = tid >> 4, tx = tid & 15;
    int u8 = g_mask_u8;

    // load Q tile transposed
    #pragma unroll
    for (int it = 0; it < 16; it++) {
        int idx = it * 256 + tid;
        int q = idx >> 6, d = idx & 63;
        Qst[d * 68 + q] = g_Q[Qbase + (size_t)q * DH + d];
    }
    if (tid < 64) { rowm[tid] = -INFINITY; rowl[tid] = 0.f; }
    float acc[4][4] = {};
    __syncthreads();

    for (int t = 0; t < NK / 64; t++) {
        int j0 = t << 6;
        // load K (transposed) and V tiles
        #pragma unroll
        for (int it = 0; it < 16; it++) {
            int idx = it * 256 + tid;
            int j = idx >> 6, d = idx & 63;
            Kst[d * 68 + j] = g_K[Kbase + (size_t)(j0 + j) * DH + d];
        }
        #pragma unroll
        for (int it = 0; it < 4; it++) {
            int idx4 = it * 256 + tid;
            int j = idx4 >> 4, d4 = idx4 & 15;
            *(float4*)&Vs[j * 64 + d4 * 4] =
                *(const float4*)&g_V[Kbase + (size_t)(j0 + j) * DH + d4 * 4];
        }
        if (tid < 64) {
            int j = j0 + tid;
            float ma = 0.f;
            if (j < NSEQ) {
                int on = u8 ? (int)m8[(size_t)b * NSEQ + j] : m32[(size_t)b * NSEQ + j];
                ma = on ? 0.f : -1e30f;
            }
            maskadd[tid] = ma;
        }
        __syncthreads();

        // S = Q K^T (4x4 per thread), + mask
        {
            float s[4][4] = {};
            #pragma unroll 8
            for (int d = 0; d < 64; d++) {
                float4 qf = *(const float4*)&Qst[d * 68 + (ty << 2)];
                float4 kf = *(const float4*)&Kst[d * 68 + (tx << 2)];
                s[0][0] += qf.x*kf.x; s[0][1] += qf.x*kf.y; s[0][2] += qf.x*kf.z; s[0][3] += qf.x*kf.w;
                s[1][0] += qf.y*kf.x; s[1][1] += qf.y*kf.y; s[1][2] += qf.y*kf.z; s[1][3] += qf.y*kf.w;
                s[2][0] += qf.z*kf.x; s[2][1] += qf.z*kf.y; s[2][2] += qf.z*kf.z; s[2][3] += qf.z*kf.w;
                s[3][0] += qf.w*kf.x; s[3][1] += qf.w*kf.y; s[3][2] += qf.w*kf.z; s[3][3] += qf.w*kf.w;
            }
            #pragma unroll
            for (int i = 0; i < 4; i++)
                #pragma unroll
                for (int jj = 0; jj < 4; jj++)
                    Ss[(ty * 4 + i) * 67 + tx * 4 + jj] = s[i][jj] + maskadd[tx * 4 + jj];
        }
        __syncthreads();

        // online softmax: 4 threads per row
        {
            int r = tid >> 2, qd = tid & 3;
            float mx = -INFINITY;
            int kbeg = qd << 4;
            #pragma unroll
            for (int k = 0; k < 16; k++) mx = fmaxf(mx, Ss[r * 67 + kbeg + k]);
            #pragma unroll
            for (int o = 1; o < 4; o <<= 1) mx = fmaxf(mx, __shfl_xor_sync(0xffffffffu, mx, o));
            float mold = rowm[r];
            float mnew = fmaxf(mold, mx);
            float a = __expf(mold - mnew);
            float part = 0.f;
            #pragma unroll
            for (int k = 0; k < 16; k++) {
                float p = __expf(Ss[r * 67 + kbeg + k] - mnew);
                Ss[r * 67 + kbeg + k] = p;
                part += p;
            }
            #pragma unroll
            for (int o = 1; o < 4; o <<= 1) part += __shfl_xor_sync(0xffffffffu, part, o);
            if (qd == 0) { rowm[r] = mnew; rowl[r] = rowl[r] * a + part; alph[r] = a; }
        }
        __syncthreads();

        // rescale + acc += P @ V
        {
            #pragma unroll
            for (int i = 0; i < 4; i++) {
                float a = alph[ty * 4 + i];
                acc[i][0] *= a; acc[i][1] *= a; acc[i][2] *= a; acc[i][3] *= a;
            }
            #pragma unroll 4
            for (int k = 0; k < 64; k++) {
                float4 vf = *(const float4*)&Vs[k * 64 + (tx << 2)];
                #pragma unroll
                for (int i = 0; i < 4; i++) {
                    float p = Ss[(ty * 4 + i) * 67 + k];
                    acc[i][0] += p * vf.x; acc[i][1] += p * vf.y;
                    acc[i][2] += p * vf.z; acc[i][3] += p * vf.w;
                }
            }
        }
        __syncthreads();
    }

    // finalize: divide by l, write O[b][i][h*64+d]
    #pragma unroll
    for (int i = 0; i < 4; i++) {
        float inv = 1.0f / rowl[ty * 4 + i];
        float4 o;
        o.x = acc[i][0] * inv; o.y = acc[i][1] * inv;
        o.z = acc[i][2] * inv; o.w = acc[i][3] * inv;
        *(float4*)&g_O[((size_t)b * MLAT + q0 + ty * 4 + i) * INNER + h * DH + (tx << 2)] = o;
    }
}

// ---------------- launch ----------------
extern "C" void kernel_launch(void* const* d_in, const int* in_sizes, int n_in,
                              void* d_out, int out_size) {
    const float* x       = (const float*)d_in[0];
    const float* latents = (const float*)d_in[1];
    const void*  mask    = d_in[2];
    const float* ln_x_g  = (const float*)d_in[3];
    const float* ln_x_b  = (const float*)d_in[4];
    const float* ln_l_g  = (const float*)d_in[5];
    const float* ln_l_b  = (const float*)d_in[6];
    const float* qn_g    = (const float*)d_in[7];
    const float* kn_g    = (const float*)d_in[8];
    const float* Wq      = (const float*)d_in[9];
    const float* Wkv     = (const float*)d_in[10];
    const float* Wlkv    = (const float*)d_in[11];
    const float* Wo      = (const float*)d_in[12];
    const float* bo      = (const float*)d_in[13];
    float* out = (float*)d_out;

    void *p_xn, *p_ln, *p_qf, *p_kvx, *p_kvl, *p_O;
    cudaGetSymbolAddress(&p_xn,  g_xn);
    cudaGetSymbolAddress(&p_ln,  g_ln);
    cudaGetSymbolAddress(&p_qf,  g_qf);
    cudaGetSymbolAddress(&p_kvx, g_kvx);
    cudaGetSymbolAddress(&p_kvl, g_kvl);
    cudaGetSymbolAddress(&p_O,   g_O);

    static const int attn_smem = ATTN_SMEM_FLOATS * 4;
    cudaFuncSetAttribute(attn_kernel, cudaFuncAttributeMaxDynamicSharedMemorySize, attn_smem);

    // mask dtype probe
    init_flag_kernel<<<1, 1>>>();
    detect_mask_kernel<<<16, 256>>>((const int*)mask);

    // layernorms
    ln_kernel<<<BB * NSEQ, 256>>>(x, ln_x_g, ln_x_b, (float*)p_xn, DIN);
    ln_kernel<<<BB * MLAT, 256>>>(latents, ln_l_g, ln_l_b, (float*)p_ln, DLAT);

    // projections
    gemm_abt_kernel<<<dim3(INNER / 64, (BB * MLAT) / 64), 256>>>(
        (const float*)p_ln, Wq, (float*)p_qf, BB * MLAT, INNER, DLAT, nullptr);
    gemm_abt_kernel<<<dim3((2 * INNER) / 64, (BB * NSEQ) / 64), 256>>>(
        (const float*)p_xn, Wkv, (float*)p_kvx, BB * NSEQ, 2 * INNER, DIN, nullptr);
    gemm_abt_kernel<<<dim3((2 * INNER) / 64, (BB * MLAT) / 64), 256>>>(
        (const float*)p_ln, Wlkv, (float*)p_kvl, BB * MLAT, 2 * INNER, DLAT, nullptr);

    // head split + rms norms
    q_scatter_kernel<<<BB * MLAT, 256>>>(qn_g);
    kv_scatter_kernel<<<BB * NK, 512>>>(kn_g);

    // attention
    attn_kernel<<<dim3(MLAT / 64, HH, BB), 256, attn_smem>>>(
        (const unsigned char*)mask, (const int*)mask);

    // output projection + bias -> d_out
    gemm_abt_kernel<<<dim3(DLAT / 64, (BB * MLAT) / 64), 256>>>(
        (const float*)p_O, Wo, out, BB * MLAT, DLAT, INNER, bo);
}

// round 16
// speedup vs baseline: 1.3509x; 1.3509x over previous
#include <cuda_runtime.h>
#include <cuda_bf16.h>
#include <mma.h>
#include <math.h>
#include <stdint.h>

using namespace nvcuda;

// ---------------- problem constants ----------------
#define BB    4
#define NSEQ  4096
#define MLAT  512
#define DIN   768
#define DLAT  1024
#define INNER 1024
#define HH    16
#define DH    64
#define NK    4608          // NSEQ + MLAT (concat along sequence)
#define LN_EPS  1e-5f
#define RMS_EPS 1e-8f
#define SCALE   0.125f      // 64^-0.5

// ---------------- scratch (static device memory; no allocations) ----------------
__device__ float g_xn [(size_t)BB*NSEQ*DIN];        // layernorm(x)
__device__ float g_ln [(size_t)BB*MLAT*DLAT];       // layernorm(latents)
__device__ float g_qf [(size_t)BB*MLAT*INNER];      // ln @ Wq^T   (flat)
__device__ float g_kvx[(size_t)BB*NSEQ*2*INNER];    // xn @ Wkv^T
__device__ float g_kvl[(size_t)BB*MLAT*2*INNER];    // ln @ Wlkv^T
__device__ float g_Q  [(size_t)BB*HH*MLAT*DH];      // rmsnorm'd * SCALE, [b][h][i][d]
__device__ float g_K  [(size_t)BB*HH*NK*DH];        // rmsnorm'd,        [b][h][j][d]
__device__ float g_V  [(size_t)BB*HH*NK*DH];        // [b][h][j][d]
__device__ float g_O  [(size_t)BB*MLAT*INNER];      // attention out, [b][i][h*64+d]
__device__ int   g_mask_u8;                         // 1 = mask is byte-packed

// =============== WMMA GEMM: C[M,N] = A[M,K] @ B[N,K]^T (+bias) ==============
// bf16 hi/lo split (3 MMAs per fragment-triple) for ~fp32 accuracy.
// CTA tile 128x128, K-chunk 64, 256 threads (8 warps, 4x2 grid of 32x64).
#define LDS 80                     // bf16 leading dim (mult of 8; 160B rows)
#define LDC 132                    // fp32 staging leading dim
#define TC_SMEM_TOTAL (4 * 128 * LDS * 2)   // 81920 bytes (>= 128*LDC*4 = 67584)

__global__ __launch_bounds__(256)
void gemm_wmma_kernel(const float* __restrict__ A, const float* __restrict__ Bm,
                      float* __restrict__ C, int M, int N, int K,
                      const float* __restrict__ bias) {
    extern __shared__ __align__(32) char smraw[];
    __nv_bfloat16* Ah = (__nv_bfloat16*)smraw;
    __nv_bfloat16* Al = Ah + 128 * LDS;
    __nv_bfloat16* Bh = Al + 128 * LDS;
    __nv_bfloat16* Bl = Bh + 128 * LDS;

    int tid = threadIdx.x;
    int wid = tid >> 5;
    int bm = blockIdx.y << 7, bn = blockIdx.x << 7;
    int wr = wid >> 1;          // 0..3 : rows 32*wr .. +32
    int wc = wid & 1;           // 0..1 : cols 64*wc .. +64

    wmma::fragment<wmma::accumulator, 16, 16, 16, float> acc[2][4];
    #pragma unroll
    for (int i = 0; i < 2; i++)
        #pragma unroll
        for (int j = 0; j < 4; j++)
            wmma::fill_fragment(acc[i][j], 0.0f);

    for (int k0 = 0; k0 < K; k0 += 64) {
        // ---- load fp32 chunk, split to bf16 hi/lo in smem ----
        #pragma unroll
        for (int t = 0; t < 8; t++) {
            int idx4 = t * 256 + tid;        // 2048 float4 groups
            int row = idx4 >> 4;             // 0..127
            int c4  = idx4 & 15;             // 0..15 (4 cols)
            float4 va = *(const float4*)&A [(size_t)(bm + row) * K + k0 + (c4 << 2)];
            float4 vb = *(const float4*)&Bm[(size_t)(bn + row) * K + k0 + (c4 << 2)];
            int e = row * LDS + (c4 << 2);   // element offset (8B aligned)
            union Pk { __nv_bfloat16 b[4]; uint2 u; };
            Pk h, l;
            h.b[0] = __float2bfloat16(va.x); l.b[0] = __float2bfloat16(va.x - __bfloat162float(h.b[0]));
            h.b[1] = __float2bfloat16(va.y); l.b[1] = __float2bfloat16(va.y - __bfloat162float(h.b[1]));
            h.b[2] = __float2bfloat16(va.z); l.b[2] = __float2bfloat16(va.z - __bfloat162float(h.b[2]));
            h.b[3] = __float2bfloat16(va.w); l.b[3] = __float2bfloat16(va.w - __bfloat162float(h.b[3]));
            *(uint2*)(Ah + e) = h.u;
            *(uint2*)(Al + e) = l.u;
            h.b[0] = __float2bfloat16(vb.x); l.b[0] = __float2bfloat16(vb.x - __bfloat162float(h.b[0]));
            h.b[1] = __float2bfloat16(vb.y); l.b[1] = __float2bfloat16(vb.y - __bfloat162float(h.b[1]));
            h.b[2] = __float2bfloat16(vb.z); l.b[2] = __float2bfloat16(vb.z - __bfloat162float(h.b[2]));
            h.b[3] = __float2bfloat16(vb.w); l.b[3] = __float2bfloat16(vb.w - __bfloat162float(h.b[3]));
            *(uint2*)(Bh + e) = h.u;
            *(uint2*)(Bl + e) = l.u;
        }
        __syncthreads();

        // ---- MMA: 4 k-steps of 16 ----
        #pragma unroll
        for (int ks = 0; ks < 4; ks++) {
            wmma::fragment<wmma::matrix_a, 16, 16, 16, __nv_bfloat16, wmma::row_major> ah[2], al[2];
            #pragma unroll
            for (int i = 0; i < 2; i++) {
                const __nv_bfloat16* ap = Ah + (wr * 32 + i * 16) * LDS + ks * 16;
                const __nv_bfloat16* lp = Al + (wr * 32 + i * 16) * LDS + ks * 16;
                wmma::load_matrix_sync(ah[i], ap, LDS);
                wmma::load_matrix_sync(al[i], lp, LDS);
            }
            #pragma unroll
            for (int j = 0; j < 4; j++) {
                wmma::fragment<wmma::matrix_b, 16, 16, 16, __nv_bfloat16, wmma::col_major> bh, bl;
                const __nv_bfloat16* bp = Bh + (wc * 64 + j * 16) * LDS + ks * 16;
                const __nv_bfloat16* qp = Bl + (wc * 64 + j * 16) * LDS + ks * 16;
                wmma::load_matrix_sync(bh, bp, LDS);
                wmma::load_matrix_sync(bl, qp, LDS);
                #pragma unroll
                for (int i = 0; i < 2; i++) {
                    wmma::mma_sync(acc[i][j], ah[i], bh, acc[i][j]);
                    wmma::mma_sync(acc[i][j], ah[i], bl, acc[i][j]);
                    wmma::mma_sync(acc[i][j], al[i], bh, acc[i][j]);
                }
            }
        }
        __syncthreads();
    }

    // ---- epilogue: stage fp32 to smem, add bias, write ----
    float* Cs = (float*)smraw;
    #pragma unroll
    for (int i = 0; i < 2; i++)
        #pragma unroll
        for (int j = 0; j < 4; j++)
            wmma::store_matrix_sync(Cs + (wr * 32 + i * 16) * LDC + wc * 64 + j * 16,
                                    acc[i][j], LDC, wmma::mem_row_major);
    __syncthreads();
    #pragma unroll
    for (int t = 0; t < 16; t++) {
        int idx4 = t * 256 + tid;        // 4096 float4 groups: 128 rows x 32 col4
        int row = idx4 >> 5;
        int c4  = idx4 & 31;
        float4 v = *(float4*)&Cs[row * LDC + (c4 << 2)];
        if (bias) {
            const float* br = bias + bn + (c4 << 2);
            v.x += br[0]; v.y += br[1]; v.z += br[2]; v.w += br[3];
        }
        *(float4*)&C[(size_t)(bm + row) * N + bn + (c4 << 2)] = v;
    }
}

// ---------------- mask dtype detection ----------------
__global__ void init_flag_kernel() { g_mask_u8 = 0; }
__global__ void detect_mask_kernel(const int* __restrict__ m) {
    int i = blockIdx.x * blockDim.x + threadIdx.x;
    if (i < 4096) {
        unsigned v = (unsigned)m[i];
        if (v > 1u) atomicExch(&g_mask_u8, 1);
    }
}

// ---------------- layernorm (one row per block, 256 threads) ----------------
__global__ __launch_bounds__(256)
void ln_kernel(const float* __restrict__ x, const float* __restrict__ g,
               const float* __restrict__ b, float* __restrict__ out, int C) {
    int row = blockIdx.x;
    const float* xr = x + (size_t)row * C;
    float* orow = out + (size_t)row * C;
    int C4 = C >> 2;
    float s = 0.f, s2 = 0.f;
    for (int i = threadIdx.x; i < C4; i += 256) {
        float4 v = ((const float4*)xr)[i];
        s  += v.x + v.y + v.z + v.w;
        s2 += v.x*v.x + v.y*v.y + v.z*v.z + v.w*v.w;
    }
    __shared__ float red0[8], red1[8];
    #pragma unroll
    for (int o = 16; o; o >>= 1) {
        s  += __shfl_xor_sync(0xffffffffu, s,  o);
        s2 += __shfl_xor_sync(0xffffffffu, s2, o);
    }
    int w = threadIdx.x >> 5, l = threadIdx.x & 31;
    if (l == 0) { red0[w] = s; red1[w] = s2; }
    __syncthreads();
    if (threadIdx.x == 0) {
        float a = 0.f, c = 0.f;
        #pragma unroll
        for (int k = 0; k < 8; k++) { a += red0[k]; c += red1[k]; }
        red0[0] = a; red1[0] = c;
    }
    __syncthreads();
    float mu  = red0[0] / (float)C;
    float var = red1[0] / (float)C - mu * mu;
    float rstd = rsqrtf(var + LN_EPS);
    for (int i = threadIdx.x; i < C4; i += 256) {
        float4 v  = ((const float4*)xr)[i];
        float4 gg = ((const float4*)g)[i];
        float4 bb = ((const float4*)b)[i];
        float4 o;
        o.x = (v.x - mu) * rstd * gg.x + bb.x;
        o.y = (v.y - mu) * rstd * gg.y + bb.y;
        o.z = (v.z - mu) * rstd * gg.z + bb.z;
        o.w = (v.w - mu) * rstd * gg.w + bb.w;
        ((float4*)orow)[i] = o;
    }
}

// ---------------- Q scatter: rmsnorm per head * SCALE, [b][h][i][d] ----------------
__global__ __launch_bounds__(256)
void q_scatter_kernel(const float* __restrict__ qn_g) {
    int row = blockIdx.x;
    int b = row >> 9, i = row & 511;
    int tid = threadIdx.x;
    int h = tid >> 4, lane = tid & 15, d0 = lane << 2;
    float4 v = *(const float4*)&g_qf[(size_t)row * INNER + h * DH + d0];
    float ss = v.x*v.x + v.y*v.y + v.z*v.z + v.w*v.w;
    #pragma unroll
    for (int o = 8; o; o >>= 1) ss += __shfl_xor_sync(0xffffffffu, ss, o);
    float norm = sqrtf(ss) * 0.125f;
    float inv = SCALE / fmaxf(norm, RMS_EPS);
    float4 g4 = *(const float4*)&qn_g[d0];
    float4 o;
    o.x = v.x * inv * g4.x; o.y = v.y * inv * g4.y;
    o.z = v.z * inv * g4.z; o.w = v.w * inv * g4.w;
    *(float4*)&g_Q[((size_t)(b * HH + h) * MLAT + i) * DH + d0] = o;
}

// ---------------- K/V scatter: K gets rmsnorm, V is a copy ----------------
__global__ __launch_bounds__(512)
void kv_scatter_kernel(const float* __restrict__ kn_g) {
    int row = blockIdx.x;
    int b = row / NK, j = row - b * NK;
    const float* src = (j < NSEQ)
        ? &g_kvx[((size_t)b * NSEQ + j) * (2 * INNER)]
        : &g_kvl[((size_t)b * MLAT + (j - NSEQ)) * (2 * INNER)];
    int tid = threadIdx.x;
    if (tid < 256) {
        int h = tid >> 4, lane = tid & 15, d0 = lane << 2;
        float4 v = *(const float4*)&src[h * DH + d0];
        float ss = v.x*v.x + v.y*v.y + v.z*v.z + v.w*v.w;
        #pragma unroll
        for (int o = 8; o; o >>= 1) ss += __shfl_xor_sync(0xffffffffu, ss, o);
        float norm = sqrtf(ss) * 0.125f;
        float inv = 1.0f / fmaxf(norm, RMS_EPS);
        float4 g4 = *(const float4*)&kn_g[d0];
        float4 o;
        o.x = v.x * inv * g4.x; o.y = v.y * inv * g4.y;
        o.z = v.z * inv * g4.z; o.w = v.w * inv * g4.w;
        *(float4*)&g_K[((size_t)(b * HH + h) * NK + j) * DH + d0] = o;
    } else {
        int t = tid - 256;
        int h = t >> 4, lane = t & 15, d0 = lane << 2;
        float4 v = *(const float4*)&src[INNER + h * DH + d0];
        *(float4*)&g_V[((size_t)(b * HH + h) * NK + j) * DH + d0] = v;
    }
}

// ---------------- flash attention: 64 queries x 64 keys per tile ----------------
#define ATTN_SMEM_FLOATS (64*68*2 + 64*64 + 64*67 + 4*64)
__global__ __launch_bounds__(256)
void attn_kernel(const unsigned char* __restrict__ m8, const int* __restrict__ m32) {
    extern __shared__ __align__(16) float sm[];
    float* Qst = sm;
    float* Kst = Qst + 64 * 68;
    float* Vs  = Kst + 64 * 68;
    float* Ss  = Vs  + 64 * 64;
    float* rowm = Ss + 64 * 67;
    float* rowl = rowm + 64;
    float* alph = rowl + 64;
    float* maskadd = alph + 64;

    int b = blockIdx.z, h = blockIdx.y;
    int q0 = blockIdx.x << 6;
    int bh = b * HH + h;
    const size_t Kbase = (size_t)bh * NK * DH;
    const size_t Qbase = ((size_t)bh * MLAT + q0) * DH;
    int tid = threadIdx.x;
    int ty = tid >> 4, tx = tid & 15;
    int u8 = g_mask_u8;

    #pragma unroll
    for (int it = 0; it < 16; it++) {
        int idx = it * 256 + tid;
        int q = idx >> 6, d = idx & 63;
        Qst[d * 68 + q] = g_Q[Qbase + (size_t)q * DH + d];
    }
    if (tid < 64) { rowm[tid] = -INFINITY; rowl[tid] = 0.f; }
    float acc[4][4] = {};
    __syncthreads();

    for (int t = 0; t < NK / 64; t++) {
        int j0 = t << 6;
        #pragma unroll
        for (int it = 0; it < 16; it++) {
            int idx = it * 256 + tid;
            int j = idx >> 6, d = idx & 63;
            Kst[d * 68 + j] = g_K[Kbase + (size_t)(j0 + j) * DH + d];
        }
        #pragma unroll
        for (int it = 0; it < 4; it++) {
            int idx4 = it * 256 + tid;
            int j = idx4 >> 4, d4 = idx4 & 15;
            *(float4*)&Vs[j * 64 + d4 * 4] =
                *(const float4*)&g_V[Kbase + (size_t)(j0 + j) * DH + d4 * 4];
        }
        if (tid < 64) {
            int j = j0 + tid;
            float ma = 0.f;
            if (j < NSEQ) {
                int on = u8 ? (int)m8[(size_t)b * NSEQ + j] : m32[(size_t)b * NSEQ + j];
                ma = on ? 0.f : -1e30f;
            }
            maskadd[tid] = ma;
        }
        __syncthreads();

        {
            float s[4][4] = {};
            #pragma unroll 8
            for (int d = 0; d < 64; d++) {
                float4 qf = *(const float4*)&Qst[d * 68 + (ty << 2)];
                float4 kf = *(const float4*)&Kst[d * 68 + (tx << 2)];
                s[0][0] += qf.x*kf.x; s[0][1] += qf.x*kf.y; s[0][2] += qf.x*kf.z; s[0][3] += qf.x*kf.w;
                s[1][0] += qf.y*kf.x; s[1][1] += qf.y*kf.y; s[1][2] += qf.y*kf.z; s[1][3] += qf.y*kf.w;
                s[2][0] += qf.z*kf.x; s[2][1] += qf.z*kf.y; s[2][2] += qf.z*kf.z; s[2][3] += qf.z*kf.w;
                s[3][0] += qf.w*kf.x; s[3][1] += qf.w*kf.y; s[3][2] += qf.w*kf.z; s[3][3] += qf.w*kf.w;
            }
            #pragma unroll
            for (int i = 0; i < 4; i++)
                #pragma unroll
                for (int jj = 0; jj < 4; jj++)
                    Ss[(ty * 4 + i) * 67 + tx * 4 + jj] = s[i][jj] + maskadd[tx * 4 + jj];
        }
        __syncthreads();

        {
            int r = tid >> 2, qd = tid & 3;
            float mx = -INFINITY;
            int kbeg = qd << 4;
            #pragma unroll
            for (int k = 0; k < 16; k++) mx = fmaxf(mx, Ss[r * 67 + kbeg + k]);
            #pragma unroll
            for (int o = 1; o < 4; o <<= 1) mx = fmaxf(mx, __shfl_xor_sync(0xffffffffu, mx, o));
            float mold = rowm[r];
            float mnew = fmaxf(mold, mx);
            float a = __expf(mold - mnew);
            float part = 0.f;
            #pragma unroll
            for (int k = 0; k < 16; k++) {
                float p = __expf(Ss[r * 67 + kbeg + k] - mnew);
                Ss[r * 67 + kbeg + k] = p;
                part += p;
            }
            #pragma unroll
            for (int o = 1; o < 4; o <<= 1) part += __shfl_xor_sync(0xffffffffu, part, o);
            if (qd == 0) { rowm[r] = mnew; rowl[r] = rowl[r] * a + part; alph[r] = a; }
        }
        __syncthreads();

        {
            #pragma unroll
            for (int i = 0; i < 4; i++) {
                float a = alph[ty * 4 + i];
                acc[i][0] *= a; acc[i][1] *= a; acc[i][2] *= a; acc[i][3] *= a;
            }
            #pragma unroll 4
            for (int k = 0; k < 64; k++) {
                float4 vf = *(const float4*)&Vs[k * 64 + (tx << 2)];
                #pragma unroll
                for (int i = 0; i < 4; i++) {
                    float p = Ss[(ty * 4 + i) * 67 + k];
                    acc[i][0] += p * vf.x; acc[i][1] += p * vf.y;
                    acc[i][2] += p * vf.z; acc[i][3] += p * vf.w;
                }
            }
        }
        __syncthreads();
    }

    #pragma unroll
    for (int i = 0; i < 4; i++) {
        float inv = 1.0f / rowl[ty * 4 + i];
        float4 o;
        o.x = acc[i][0] * inv; o.y = acc[i][1] * inv;
        o.z = acc[i][2] * inv; o.w = acc[i][3] * inv;
        *(float4*)&g_O[((size_t)b * MLAT + q0 + ty * 4 + i) * INNER + h * DH + (tx << 2)] = o;
    }
}

// ---------------- launch ----------------
extern "C" void kernel_launch(void* const* d_in, const int* in_sizes, int n_in,
                              void* d_out, int out_size) {
    const float* x       = (const float*)d_in[0];
    const float* latents = (const float*)d_in[1];
    const void*  mask    = d_in[2];
    const float* ln_x_g  = (const float*)d_in[3];
    const float* ln_x_b  = (const float*)d_in[4];
    const float* ln_l_g  = (const float*)d_in[5];
    const float* ln_l_b  = (const float*)d_in[6];
    const float* qn_g    = (const float*)d_in[7];
    const float* kn_g    = (const float*)d_in[8];
    const float* Wq      = (const float*)d_in[9];
    const float* Wkv     = (const float*)d_in[10];
    const float* Wlkv    = (const float*)d_in[11];
    const float* Wo      = (const float*)d_in[12];
    const float* bo      = (const float*)d_in[13];
    float* out = (float*)d_out;

    void *p_xn, *p_ln, *p_qf, *p_kvx, *p_kvl, *p_O;
    cudaGetSymbolAddress(&p_xn,  g_xn);
    cudaGetSymbolAddress(&p_ln,  g_ln);
    cudaGetSymbolAddress(&p_qf,  g_qf);
    cudaGetSymbolAddress(&p_kvx, g_kvx);
    cudaGetSymbolAddress(&p_kvl, g_kvl);
    cudaGetSymbolAddress(&p_O,   g_O);

    static const int attn_smem = ATTN_SMEM_FLOATS * 4;
    cudaFuncSetAttribute(attn_kernel, cudaFuncAttributeMaxDynamicSharedMemorySize, attn_smem);
    cudaFuncSetAttribute(gemm_wmma_kernel, cudaFuncAttributeMaxDynamicSharedMemorySize, TC_SMEM_TOTAL);

    // mask dtype probe
    init_flag_kernel<<<1, 1>>>();
    detect_mask_kernel<<<16, 256>>>((const int*)mask);

    // layernorms
    ln_kernel<<<BB * NSEQ, 256>>>(x, ln_x_g, ln_x_b, (float*)p_xn, DIN);
    ln_kernel<<<BB * MLAT, 256>>>(latents, ln_l_g, ln_l_b, (float*)p_ln, DLAT);

    // projections (WMMA bf16x3)
    gemm_wmma_kernel<<<dim3(INNER / 128, (BB * MLAT) / 128), 256, TC_SMEM_TOTAL>>>(
        (const float*)p_ln, Wq, (float*)p_qf, BB * MLAT, INNER, DLAT, nullptr);
    gemm_wmma_kernel<<<dim3((2 * INNER) / 128, (BB * NSEQ) / 128), 256, TC_SMEM_TOTAL>>>(
        (const float*)p_xn, Wkv, (float*)p_kvx, BB * NSEQ, 2 * INNER, DIN, nullptr);
    gemm_wmma_kernel<<<dim3((2 * INNER) / 128, (BB * MLAT) / 128), 256, TC_SMEM_TOTAL>>>(
        (const float*)p_ln, Wlkv, (float*)p_kvl, BB * MLAT, 2 * INNER, DLAT, nullptr);

    // head split + rms norms
    q_scatter_kernel<<<BB * MLAT, 256>>>(qn_g);
    kv_scatter_kernel<<<BB * NK, 512>>>(kn_g);

    // attention
    attn_kernel<<<dim3(MLAT / 64, HH, BB), 256, attn_smem>>>(
        (const unsigned char*)mask, (const int*)mask);

    // output projection + bias -> d_out (WMMA bf16x3)
    gemm_wmma_kernel<<<dim3(DLAT / 128, (BB * MLAT) / 128), 256, TC_SMEM_TOTAL>>>(
        (const float*)p_O, Wo, out, BB * MLAT, DLAT, INNER, bo);
}